// round 4
// baseline (speedup 1.0000x reference)
#include <cuda_runtime.h>
#include <cuda_bf16.h>
#include <math.h>
#include <stdint.h>

// ---------------------------------------------------------------------------
// bs=16, c_in=c_out=512, w_dim=512, L=2048, k=3, UP=DOWN=2, 17-tap Kaiser LPF
// Conv: single-pass TF32 implicit GEMM on mma.sync.m16n8k8 (compute_103-safe).
// ---------------------------------------------------------------------------

#define BS   16
#define CIN  512
#define COUT 512
#define LEN  2048
#define WDIM 512

// ---------------- device scratch -------------------------------------------
__device__ float g_cond[BS * CIN];
__device__ float g_sx[BS * CIN];          // cond * inv_s * rsqrt(norm_ema)
__device__ float g_scale[BS * COUT];      // d[b,o] * invw[o]
__device__ float g_inv_s;
__device__ float g_y[BS * COUT * LEN];    // conv output (64 MB)

struct Filt { float up[17]; float dn[17]; };

// ---------------- helpers --------------------------------------------------
__device__ __forceinline__ uint32_t f2tf32(float v) {
    uint32_t r;
    asm("cvt.rna.tf32.f32 %0, %1;" : "=r"(r) : "f"(v));
    return r;
}

__device__ __forceinline__ void mma_tf32(float* c, const uint32_t a[4],
                                         uint32_t b0, uint32_t b1) {
    asm volatile(
        "mma.sync.aligned.m16n8k8.row.col.f32.tf32.tf32.f32 "
        "{%0,%1,%2,%3}, {%4,%5,%6,%7}, {%8,%9}, {%0,%1,%2,%3};"
        : "+f"(c[0]), "+f"(c[1]), "+f"(c[2]), "+f"(c[3])
        : "r"(a[0]), "r"(a[1]), "r"(a[2]), "r"(a[3]), "r"(b0), "r"(b1));
}

// ---------------- K1: cond[b,c] (warp per (c,b)) ---------------------------
__global__ void cond_kernel(const float* __restrict__ w,
                            const float* __restrict__ aw,
                            const float* __restrict__ ab) {
    int gw = blockIdx.x * 8 + (threadIdx.x >> 5);  // 8192 warps = (c,b)
    int lane = threadIdx.x & 31;
    int c = gw & (CIN - 1);
    int b = gw >> 9;
    float acc = 0.f;
#pragma unroll
    for (int t = 0; t < 16; t++)
        acc = fmaf(aw[c * WDIM + lane + 32 * t], w[b * WDIM + lane + 32 * t], acc);
#pragma unroll
    for (int s = 16; s; s >>= 1) acc += __shfl_xor_sync(0xffffffffu, acc, s);
    if (lane == 0) g_cond[b * CIN + c] = acc + ab[c];
}

// ---------------- K2: inv_s ------------------------------------------------
__global__ void reduce_cond_kernel() {
    __shared__ float sm[256];
    float s = 0.f;
    for (int i = threadIdx.x; i < BS * CIN; i += 256) {
        float v = g_cond[i];
        s = fmaf(v, v, s);
    }
    sm[threadIdx.x] = s;
    __syncthreads();
    for (int off = 128; off; off >>= 1) {
        if (threadIdx.x < off) sm[threadIdx.x] += sm[threadIdx.x + off];
        __syncthreads();
    }
    if (threadIdx.x == 0) g_inv_s = rsqrtf(sm[0] / (float)(BS * CIN));
}

// ---------------- K3: g_sx = cond * inv_s * rsqrt(norm_ema) ---------------
__global__ void scale_s_kernel(const float* __restrict__ norm_ema) {
    int idx = blockIdx.x * blockDim.x + threadIdx.x;
    if (idx >= BS * CIN) return;
    g_sx[idx] = g_cond[idx] * g_inv_s * rsqrtf(norm_ema[0]);
}

// ---------------- K4: fused weight stats + demod scale ---------------------
__global__ void __launch_bounds__(128)
wdemod_kernel(const float* __restrict__ cw) {
    int o = blockIdx.x;
    int tid = threadIdx.x;
    __shared__ float red[128];
    __shared__ float sm2[16 * 128];
    __shared__ float s_invw;

    float w2[4];
    float sumw2 = 0.f;
#pragma unroll
    for (int j = 0; j < 4; j++) {
        int i = tid * 4 + j;
        const float* p = cw + (size_t)o * (CIN * 3) + i * 3;
        w2[j] = p[0] * p[0] + p[1] * p[1] + p[2] * p[2];
        sumw2 += w2[j];
    }
    red[tid] = sumw2;
    __syncthreads();
    for (int off = 64; off; off >>= 1) {
        if (tid < off) red[tid] += red[tid + off];
        __syncthreads();
    }
    if (tid == 0) s_invw = rsqrtf(red[0] / (float)(CIN * 3));
    __syncthreads();
    float invw = s_invw;

    float acc[16];
#pragma unroll
    for (int b = 0; b < 16; b++) acc[b] = 0.f;
#pragma unroll
    for (int j = 0; j < 4; j++) {
        int i = tid * 4 + j;
#pragma unroll
        for (int b = 0; b < 16; b++) {
            float cv = g_cond[b * CIN + i];
            acc[b] = fmaf(w2[j], cv * cv, acc[b]);
        }
    }
#pragma unroll
    for (int b = 0; b < 16; b++) sm2[b * 128 + tid] = acc[b];
    __syncthreads();
    for (int off = 64; off; off >>= 1) {
        for (int b = (tid >> 6); b < 16; b += 2) {
            int t = tid & 63;
            if (t < off) sm2[b * 128 + t] += sm2[b * 128 + t + off];
        }
        __syncthreads();
    }
    if (tid < 16) {
        float inv_s = g_inv_s;
        float f = invw * invw * inv_s * inv_s;
        g_scale[tid * COUT + o] = rsqrtf(f * sm2[tid * 128] + 1e-8f) * invw;
    }
}

// ---------------- K5: TF32 modulated conv ----------------------------------
// Block: 128 o x 128 l, one batch. 8 warps = (wm 0..3) x (wn 0..1),
// warp tile 32 o x 64 l = 2 m16 x 8 n8 fragments. K chunk CI=16 channels,
// per chunk: 3 taps x 2 k8 = 6 mma k-steps.
// xsm: [16 ch][136 l] (l covers l0-4 .. l0+131; need l0-1 .. l0+129)
// wsm: [3*128 rows][stride 20] fp32 (tf32-rounded), style scale folded in.
#define CI   16
#define XROW 136
#define WROW 20

__global__ void __launch_bounds__(256)
conv_tf32_kernel(const float* __restrict__ x,
                 const float* __restrict__ conv_w,
                 const float* __restrict__ conv_b) {
    __shared__ float xsm[CI * XROW];            // 8704 B
    __shared__ float wsm[3 * 128 * WROW];       // 30720 B

    int tid  = threadIdx.x;
    int warp = tid >> 5;
    int lane = tid & 31;
    int grp  = lane >> 2;   // 0..7
    int tig  = lane & 3;    // 0..3
    int wm   = warp >> 1;   // 0..3
    int wn   = warp & 1;    // 0..1

    int l0 = blockIdx.x * 128;
    int o0 = blockIdx.y * 128;
    int b  = blockIdx.z;

    float acc[2][8][4];
#pragma unroll
    for (int mt = 0; mt < 2; mt++)
#pragma unroll
        for (int nt = 0; nt < 8; nt++)
#pragma unroll
            for (int r = 0; r < 4; r++) acc[mt][nt][r] = 0.f;

    const float* xb  = x + (size_t)b * CIN * LEN;
    const float* sxb = g_sx + b * CIN;

    for (int ic = 0; ic < CIN / CI; ic++) {
        int i0 = ic * CI;
        // ---- stage x (raw -> tf32): 16 rows x 136 ----
        for (int idx = tid; idx < CI * XROW; idx += 256) {
            int ch = idx / XROW;
            int p  = idx - ch * XROW;
            int gl = l0 - 4 + p;
            float v = 0.f;
            if (gl >= 0 && gl < LEN) v = xb[(i0 + ch) * LEN + gl];
            ((uint32_t*)xsm)[idx] = f2tf32(v);
        }
        // ---- stage w * style -> tf32: [kk*128+o][i] ----
        for (int idx = tid; idx < 128 * CI * 3; idx += 256) {
            int o  = idx / 48;
            int r  = idx - o * 48;
            int i  = r / 3;
            int kk = r - i * 3;
            float v = conv_w[(size_t)(o0 + o) * (CIN * 3) + (i0 + i) * 3 + kk]
                      * sxb[i0 + i];
            ((uint32_t*)wsm)[(kk * 128 + o) * WROW + i] = f2tf32(v);
        }
        __syncthreads();

#pragma unroll
        for (int kk = 0; kk < 3; kk++) {
#pragma unroll
            for (int k8 = 0; k8 < 2; k8++) {
                uint32_t a[2][4];
#pragma unroll
                for (int mt = 0; mt < 2; mt++) {
                    const uint32_t* wp = (const uint32_t*)wsm +
                        (kk * 128 + wm * 32 + mt * 16 + grp) * WROW + k8 * 8 + tig;
                    a[mt][0] = wp[0];
                    a[mt][1] = wp[8 * WROW];
                    a[mt][2] = wp[4];
                    a[mt][3] = wp[8 * WROW + 4];
                }
                const uint32_t* xp = (const uint32_t*)xsm +
                    (k8 * 8 + tig) * XROW + wn * 64 + grp + kk + 3;
#pragma unroll
                for (int nt = 0; nt < 8; nt++) {
                    uint32_t b0 = xp[nt * 8];
                    uint32_t b1 = xp[nt * 8 + 4 * XROW];
                    mma_tf32(acc[0][nt], a[0], b0, b1);
                    mma_tf32(acc[1][nt], a[1], b0, b1);
                }
            }
        }
        __syncthreads();
    }

    // ---- epilogue: per-o demod scale + bias -> g_y ----
#pragma unroll
    for (int mt = 0; mt < 2; mt++) {
        int oA = o0 + wm * 32 + mt * 16 + grp;
        int oB = oA + 8;
        float scA = g_scale[b * COUT + oA], bbA = conv_b[oA];
        float scB = g_scale[b * COUT + oB], bbB = conv_b[oB];
#pragma unroll
        for (int nt = 0; nt < 8; nt++) {
            int l = l0 + wn * 64 + nt * 8 + 2 * tig;
            float2 vA = make_float2(fmaf(acc[mt][nt][0], scA, bbA),
                                    fmaf(acc[mt][nt][1], scA, bbA));
            float2 vB = make_float2(fmaf(acc[mt][nt][2], scB, bbB),
                                    fmaf(acc[mt][nt][3], scB, bbB));
            *(float2*)&g_y[((size_t)(b * COUT + oA)) * LEN + l] = vA;
            *(float2*)&g_y[((size_t)(b * COUT + oB)) * LEN + l] = vB;
        }
    }
}

// ---------------- K6: fused up-LPF -> lrelu*sqrt2 -> down-LPF -> ::2 -------
__global__ void __launch_bounds__(256)
resample_kernel(float* __restrict__ out, Filt F) {
    __shared__ float ysm[LEN + 16];
    __shared__ float usm[2 * LEN + 16];
    int bc = blockIdx.x;
    const float* yrow = g_y + (size_t)bc * LEN;
    int t = threadIdx.x;

    if (t < 8) {
        ysm[t] = 0.f; ysm[LEN + 8 + t] = 0.f;
        usm[t] = 0.f; usm[2 * LEN + 8 + t] = 0.f;
    }
    for (int i = t; i < LEN; i += 256) ysm[8 + i] = yrow[i];
    __syncthreads();

    const float s2 = 1.41421356237f;
    for (int q = t; q < LEN; q += 256) {
        float ue = 0.f;
#pragma unroll
        for (int p = 0; p < 9; p++) ue = fmaf(F.up[2 * p], ysm[q + 4 + p], ue);
        float uo = 0.f;
#pragma unroll
        for (int p = 0; p < 8; p++) uo = fmaf(F.up[2 * p + 1], ysm[q + 5 + p], uo);
        usm[8 + 2 * q]     = (ue > 0.f ? ue : 0.1f * ue) * s2;
        usm[8 + 2 * q + 1] = (uo > 0.f ? uo : 0.1f * uo) * s2;
    }
    __syncthreads();

    float* orow = out + (size_t)bc * LEN;
    for (int tt = t; tt < LEN; tt += 256) {
        float z = 0.f;
#pragma unroll
        for (int k = 0; k < 17; k++) z = fmaf(F.dn[k], usm[2 * tt + k], z);
        orow[tt] = z;
    }
}

// ---------------- host: Kaiser-sinc filter ---------------------------------
static double bessel_i0(double x) {
    double s = 1.0, term = 1.0;
    for (int k = 1; k < 64; k++) {
        double h = x / (2.0 * k);
        term *= h * h;
        s += term;
        if (term < 1e-18 * s) break;
    }
    return s;
}
static void make_filter(float* f) {
    const double PI = 3.14159265358979323846;
    double i0b = bessel_i0(2.5);
    for (int i = 0; i < 17; i++) {
        int n = i - 8;
        float fv;
        if (n == 0) fv = 0.5f;
        else fv = (float)sin(0.5 * PI * (double)n) / ((float)(PI * (double)n) + 1e-8f);
        double r = (double)n / 8.0;
        double win = bessel_i0(2.5 * sqrt(1.0 - r * r)) / i0b;
        f[i] = (float)win * fv;
    }
}

// ---------------- launcher -------------------------------------------------
extern "C" void kernel_launch(void* const* d_in, const int* in_sizes, int n_in,
                              void* d_out, int out_size) {
    const float* x        = (const float*)d_in[0];
    const float* w        = (const float*)d_in[1];
    const float* affine_w = (const float*)d_in[2];
    const float* affine_b = (const float*)d_in[3];
    const float* conv_w   = (const float*)d_in[4];
    const float* conv_b   = (const float*)d_in[5];
    const float* norm_ema = (const float*)d_in[6];
    float* out = (float*)d_out;

    Filt F;
    make_filter(F.up);
    make_filter(F.dn);

    cond_kernel<<<1024, 256>>>(w, affine_w, affine_b);
    reduce_cond_kernel<<<1, 256>>>();
    scale_s_kernel<<<32, 256>>>(norm_ema);
    wdemod_kernel<<<COUT, 128>>>(conv_w);

    dim3 cgrid(LEN / 128, COUT / 128, BS);
    conv_tf32_kernel<<<cgrid, 256>>>(x, conv_w, conv_b);

    resample_kernel<<<BS * COUT, 256>>>(out, F);
}

// round 5
// speedup vs baseline: 1.4602x; 1.4602x over previous
#include <cuda_runtime.h>
#include <cuda_fp16.h>
#include <math.h>
#include <stdint.h>

// ---------------------------------------------------------------------------
// bs=16, c_in=c_out=512, w_dim=512, L=2048, k=3, UP=DOWN=2, 17-tap Kaiser LPF
// Conv: FP16 2-slot split implicit GEMM on mma.sync.m16n8k16.f32.f16.f16.f32
//   slots per channel j: A:{w_hi, w_lo}  B:{x_h, x_h}
//   => computes sum (w_hi+w_lo)*x_h = w(~22bit) * x_h ; err ~ 2^-11/sqrt(3)
// ---------------------------------------------------------------------------

#define BS   16
#define CIN  512
#define COUT 512
#define LEN  2048
#define WDIM 512

// ---------------- device scratch -------------------------------------------
__device__ float    g_cond[BS * CIN];
__device__ float    g_sx[BS * CIN];          // cond * inv_s * rsqrt(norm_ema)
__device__ float    g_scale[BS * COUT];      // d[b,o] * invw[o]
__device__ float    g_inv_s;
__device__ float    g_y[BS * COUT * LEN];    // conv output (64 MB)
__device__ __half   g_xh[BS * CIN * LEN];    // fp16 hi plane of scaled x (32 MB)
__device__ uint32_t g_wsp[3 * COUT * CIN];   // packed (w_hi, w_lo) fp16, [kk][o][i]

struct Filt { float up[17]; float dn[17]; };

// ---------------- K1: cond[b,c] (warp per (c,b)) ---------------------------
__global__ void cond_kernel(const float* __restrict__ w,
                            const float* __restrict__ aw,
                            const float* __restrict__ ab) {
    int gw = blockIdx.x * 8 + (threadIdx.x >> 5);  // 8192 warps = (c,b)
    int lane = threadIdx.x & 31;
    int c = gw & (CIN - 1);
    int b = gw >> 9;
    float acc = 0.f;
#pragma unroll
    for (int t = 0; t < 16; t++)
        acc = fmaf(aw[c * WDIM + lane + 32 * t], w[b * WDIM + lane + 32 * t], acc);
#pragma unroll
    for (int s = 16; s; s >>= 1) acc += __shfl_xor_sync(0xffffffffu, acc, s);
    if (lane == 0) g_cond[b * CIN + c] = acc + ab[c];
}

// ---------------- K2: inv_s ------------------------------------------------
__global__ void reduce_cond_kernel() {
    __shared__ float sm[256];
    float s = 0.f;
    for (int i = threadIdx.x; i < BS * CIN; i += 256) {
        float v = g_cond[i];
        s = fmaf(v, v, s);
    }
    sm[threadIdx.x] = s;
    __syncthreads();
    for (int off = 128; off; off >>= 1) {
        if (threadIdx.x < off) sm[threadIdx.x] += sm[threadIdx.x + off];
        __syncthreads();
    }
    if (threadIdx.x == 0) g_inv_s = rsqrtf(sm[0] / (float)(BS * CIN));
}

// ---------------- K3: g_sx = cond * inv_s * rsqrt(norm_ema) ----------------
__global__ void scale_s_kernel(const float* __restrict__ norm_ema) {
    int idx = blockIdx.x * blockDim.x + threadIdx.x;
    if (idx >= BS * CIN) return;
    g_sx[idx] = g_cond[idx] * g_inv_s * rsqrtf(norm_ema[0]);
}

// ---------------- K4: fused weight stats + demod scale ---------------------
__global__ void __launch_bounds__(128)
wdemod_kernel(const float* __restrict__ cw) {
    int o = blockIdx.x;
    int tid = threadIdx.x;
    __shared__ float red[128];
    __shared__ float sm2[16 * 128];
    __shared__ float s_invw;

    float w2[4];
    float sumw2 = 0.f;
#pragma unroll
    for (int j = 0; j < 4; j++) {
        int i = tid * 4 + j;
        const float* p = cw + (size_t)o * (CIN * 3) + i * 3;
        w2[j] = p[0] * p[0] + p[1] * p[1] + p[2] * p[2];
        sumw2 += w2[j];
    }
    red[tid] = sumw2;
    __syncthreads();
    for (int off = 64; off; off >>= 1) {
        if (tid < off) red[tid] += red[tid + off];
        __syncthreads();
    }
    if (tid == 0) s_invw = rsqrtf(red[0] / (float)(CIN * 3));
    __syncthreads();
    float invw = s_invw;

    float acc[16];
#pragma unroll
    for (int b = 0; b < 16; b++) acc[b] = 0.f;
#pragma unroll
    for (int j = 0; j < 4; j++) {
        int i = tid * 4 + j;
#pragma unroll
        for (int b = 0; b < 16; b++) {
            float cv = g_cond[b * CIN + i];
            acc[b] = fmaf(w2[j], cv * cv, acc[b]);
        }
    }
#pragma unroll
    for (int b = 0; b < 16; b++) sm2[b * 128 + tid] = acc[b];
    __syncthreads();
    for (int off = 64; off; off >>= 1) {
        for (int b = (tid >> 6); b < 16; b += 2) {
            int t = tid & 63;
            if (t < off) sm2[b * 128 + t] += sm2[b * 128 + t + off];
        }
        __syncthreads();
    }
    if (tid < 16) {
        float inv_s = g_inv_s;
        float f = invw * invw * inv_s * inv_s;
        g_scale[tid * COUT + o] = rsqrtf(f * sm2[tid * 128] + 1e-8f) * invw;
    }
}

// ---------------- K5a: split weights -> packed (hi,lo) fp16 [kk][o][i] -----
__global__ void split_w_kernel(const float* __restrict__ cw) {
    int idx = blockIdx.x * blockDim.x + threadIdx.x;
    if (idx >= 3 * COUT * CIN) return;
    int i  = idx & (CIN - 1);
    int o  = (idx >> 9) & (COUT - 1);
    int kk = idx >> 18;
    float v = cw[(size_t)(o * CIN + i) * 3 + kk];
    __half h = __float2half_rn(v);
    __half l = __float2half_rn(v - __half2float(h));
    g_wsp[idx] = (uint32_t)__half_as_ushort(h) |
                 ((uint32_t)__half_as_ushort(l) << 16);
}

// ---------------- K5b: scaled x -> fp16 hi plane ---------------------------
__global__ void split_x_kernel(const float* __restrict__ x) {
    int idx4 = blockIdx.x * blockDim.x + threadIdx.x;   // quad index
    if (idx4 >= (BS * CIN * LEN) / 4) return;
    int row = idx4 >> 9;                                 // b*CIN + c
    float sc = g_sx[row];
    float4 v = ((const float4*)x)[idx4];
    uint32_t p0 = (uint32_t)__half_as_ushort(__float2half_rn(v.x * sc)) |
                  ((uint32_t)__half_as_ushort(__float2half_rn(v.y * sc)) << 16);
    uint32_t p1 = (uint32_t)__half_as_ushort(__float2half_rn(v.z * sc)) |
                  ((uint32_t)__half_as_ushort(__float2half_rn(v.w * sc)) << 16);
    ((uint2*)g_xh)[idx4] = make_uint2(p0, p1);
}

// ---------------- K6: FP16 modulated conv via mma.sync ---------------------
// Block tile: 128 o x 128 l, one batch. 8 warps (wm 0..3 x wn 0..1),
// warp tile 32 o x 64 l = 2 m16 x 8 n8 fragments.
// K per 16-ch chunk: 32 slots (2/channel) = 2 k16 tiles; 3 taps via B row shift.
#define BO   128
#define BLT  128
#define CI   16
#define XPAD 40                      // halves per smem row (80 B)
#define XROWS (BLT + 2)
#define WROWS (3 * BO)

__device__ __forceinline__ void mma16816h(float* c, const uint32_t a[4],
                                          uint32_t b0, uint32_t b1) {
    asm volatile(
        "mma.sync.aligned.m16n8k16.row.col.f32.f16.f16.f32 "
        "{%0,%1,%2,%3}, {%4,%5,%6,%7}, {%8,%9}, {%0,%1,%2,%3};"
        : "+f"(c[0]), "+f"(c[1]), "+f"(c[2]), "+f"(c[3])
        : "r"(a[0]), "r"(a[1]), "r"(a[2]), "r"(a[3]), "r"(b0), "r"(b1));
}

__global__ void __launch_bounds__(256)
conv_mma_kernel(const float* __restrict__ conv_b) {
    __shared__ unsigned short xsm[XROWS * XPAD];   // 10400 B
    __shared__ unsigned short wsm[WROWS * XPAD];   // 30720 B

    int tid  = threadIdx.x;
    int warp = tid >> 5;
    int lane = tid & 31;
    int grp  = lane >> 2;
    int tig  = lane & 3;
    int wm   = warp >> 1;   // 0..3
    int wn   = warp & 1;    // 0..1

    int l0 = blockIdx.x * BLT;
    int o0 = blockIdx.y * BO;
    int b  = blockIdx.z;

    float acc[2][8][4];
#pragma unroll
    for (int mt = 0; mt < 2; mt++)
#pragma unroll
        for (int nt = 0; nt < 8; nt++)
#pragma unroll
            for (int r = 0; r < 4; r++) acc[mt][nt][r] = 0.f;

    const __half* xb = g_xh + (size_t)b * CIN * LEN;

    for (int ic = 0; ic < CIN / CI; ic++) {
        int i0 = ic * CI;
        // ---- stage x: xsm[n][2j],[2j+1] = x_h duplicated ----
        for (int idx = tid; idx < CI * XROWS; idx += 256) {
            int j = idx / XROWS;
            int n = idx - j * XROWS;
            int gl = l0 - 1 + n;
            unsigned short hv = 0;
            if (gl >= 0 && gl < LEN)
                hv = __half_as_ushort(xb[(i0 + j) * LEN + gl]);
            uint32_t pair = (uint32_t)hv | ((uint32_t)hv << 16);
            *(uint32_t*)&xsm[n * XPAD + 2 * j] = pair;
        }
        // ---- stage w: wsm[kk*BO+o][2j],[2j+1] = (w_hi, w_lo) ----
        for (int idx = tid; idx < 3 * BO * CI; idx += 256) {
            int j  = idx & (CI - 1);
            int rest = idx >> 4;
            int o  = rest & (BO - 1);
            int kk = rest >> 7;
            uint32_t v = g_wsp[((kk * COUT) + o0 + o) * CIN + i0 + j];
            *(uint32_t*)&wsm[(kk * BO + o) * XPAD + 2 * j] = v;
        }
        __syncthreads();

#pragma unroll
        for (int kk = 0; kk < 3; kk++) {
#pragma unroll
            for (int k16 = 0; k16 < 2; k16++) {
                int col = k16 * 16 + 2 * tig;
                uint32_t a[2][4];
#pragma unroll
                for (int mt = 0; mt < 2; mt++) {
                    const unsigned short* wp =
                        wsm + (kk * BO + wm * 32 + mt * 16 + grp) * XPAD + col;
                    a[mt][0] = *(const uint32_t*)(wp);
                    a[mt][1] = *(const uint32_t*)(wp + 8 * XPAD);
                    a[mt][2] = *(const uint32_t*)(wp + 8);
                    a[mt][3] = *(const uint32_t*)(wp + 8 * XPAD + 8);
                }
#pragma unroll
                for (int nt = 0; nt < 8; nt++) {
                    const unsigned short* xp =
                        xsm + (wn * 64 + nt * 8 + grp + kk) * XPAD + col;
                    uint32_t b0 = *(const uint32_t*)(xp);
                    uint32_t b1 = *(const uint32_t*)(xp + 8);
                    mma16816h(acc[0][nt], a[0], b0, b1);
                    mma16816h(acc[1][nt], a[1], b0, b1);
                }
            }
        }
        __syncthreads();
    }

    // ---- epilogue: per-o demod scale + bias -> g_y ----
#pragma unroll
    for (int mt = 0; mt < 2; mt++) {
        int oA = o0 + wm * 32 + mt * 16 + grp;
        int oB = oA + 8;
        float scA = g_scale[b * COUT + oA], bbA = conv_b[oA];
        float scB = g_scale[b * COUT + oB], bbB = conv_b[oB];
#pragma unroll
        for (int nt = 0; nt < 8; nt++) {
            int l = l0 + wn * 64 + nt * 8 + 2 * tig;
            float2 vA = make_float2(fmaf(acc[mt][nt][0], scA, bbA),
                                    fmaf(acc[mt][nt][1], scA, bbA));
            float2 vB = make_float2(fmaf(acc[mt][nt][2], scB, bbB),
                                    fmaf(acc[mt][nt][3], scB, bbB));
            *(float2*)&g_y[((size_t)(b * COUT + oA)) * LEN + l] = vA;
            *(float2*)&g_y[((size_t)(b * COUT + oB)) * LEN + l] = vB;
        }
    }
}

// ---------------- K7: fused up-LPF -> lrelu*sqrt2 -> down-LPF -> ::2 -------
__global__ void __launch_bounds__(256)
resample_kernel(float* __restrict__ out, Filt F) {
    __shared__ float ysm[LEN + 16];
    __shared__ float usm[2 * LEN + 16];
    int bc = blockIdx.x;
    const float* yrow = g_y + (size_t)bc * LEN;
    int t = threadIdx.x;

    if (t < 8) {
        ysm[t] = 0.f; ysm[LEN + 8 + t] = 0.f;
        usm[t] = 0.f; usm[2 * LEN + 8 + t] = 0.f;
    }
    for (int i = t; i < LEN; i += 256) ysm[8 + i] = yrow[i];
    __syncthreads();

    const float s2 = 1.41421356237f;
    for (int q = t; q < LEN; q += 256) {
        float ue = 0.f;
#pragma unroll
        for (int p = 0; p < 9; p++) ue = fmaf(F.up[2 * p], ysm[q + 4 + p], ue);
        float uo = 0.f;
#pragma unroll
        for (int p = 0; p < 8; p++) uo = fmaf(F.up[2 * p + 1], ysm[q + 5 + p], uo);
        usm[8 + 2 * q]     = (ue > 0.f ? ue : 0.1f * ue) * s2;
        usm[8 + 2 * q + 1] = (uo > 0.f ? uo : 0.1f * uo) * s2;
    }
    __syncthreads();

    float* orow = out + (size_t)bc * LEN;
    for (int tt = t; tt < LEN; tt += 256) {
        float z = 0.f;
#pragma unroll
        for (int k = 0; k < 17; k++) z = fmaf(F.dn[k], usm[2 * tt + k], z);
        orow[tt] = z;
    }
}

// ---------------- host: Kaiser-sinc filter ---------------------------------
static double bessel_i0(double x) {
    double s = 1.0, term = 1.0;
    for (int k = 1; k < 64; k++) {
        double h = x / (2.0 * k);
        term *= h * h;
        s += term;
        if (term < 1e-18 * s) break;
    }
    return s;
}
static void make_filter(float* f) {
    const double PI = 3.14159265358979323846;
    double i0b = bessel_i0(2.5);
    for (int i = 0; i < 17; i++) {
        int n = i - 8;
        float fv;
        if (n == 0) fv = 0.5f;
        else fv = (float)sin(0.5 * PI * (double)n) / ((float)(PI * (double)n) + 1e-8f);
        double r = (double)n / 8.0;
        double win = bessel_i0(2.5 * sqrt(1.0 - r * r)) / i0b;
        f[i] = (float)win * fv;
    }
}

// ---------------- launcher -------------------------------------------------
extern "C" void kernel_launch(void* const* d_in, const int* in_sizes, int n_in,
                              void* d_out, int out_size) {
    const float* x        = (const float*)d_in[0];
    const float* w        = (const float*)d_in[1];
    const float* affine_w = (const float*)d_in[2];
    const float* affine_b = (const float*)d_in[3];
    const float* conv_w   = (const float*)d_in[4];
    const float* conv_b   = (const float*)d_in[5];
    const float* norm_ema = (const float*)d_in[6];
    float* out = (float*)d_out;

    Filt F;
    make_filter(F.up);
    make_filter(F.dn);

    cond_kernel<<<1024, 256>>>(w, affine_w, affine_b);
    reduce_cond_kernel<<<1, 256>>>();
    scale_s_kernel<<<32, 256>>>(norm_ema);
    wdemod_kernel<<<COUT, 128>>>(conv_w);
    split_w_kernel<<<(3 * COUT * CIN + 255) / 256, 256>>>(conv_w);
    split_x_kernel<<<(BS * CIN * LEN / 4 + 255) / 256, 256>>>(x);

    dim3 cgrid(LEN / BLT, COUT / BO, BS);
    conv_mma_kernel<<<cgrid, 256>>>(conv_b);

    resample_kernel<<<BS * COUT, 256>>>(out, F);
}

// round 6
// speedup vs baseline: 2.1625x; 1.4809x over previous
#include <cuda_runtime.h>
#include <cuda_fp16.h>
#include <math.h>
#include <stdint.h>

// ---------------------------------------------------------------------------
// bs=16, c_in=c_out=512, w_dim=512, L=2048, k=3, UP=DOWN=2, 17-tap Kaiser LPF
// Conv: pure FP16 implicit GEMM on mma.sync.m16n8k16.f32.f16.f16.f32
//   (fp32 accumulate; w,x fp16-rounded; expected rel_err ~3.5e-4)
// ---------------------------------------------------------------------------

#define BS   16
#define CIN  512
#define COUT 512
#define LEN  2048
#define WDIM 512

// ---------------- device scratch -------------------------------------------
__device__ float  g_cond[BS * CIN];
__device__ float  g_sx[BS * CIN];          // cond * inv_s * rsqrt(norm_ema)
__device__ float  g_scale[BS * COUT];      // d[b,o] * invw[o]
__device__ float  g_inv_s;
__device__ float  g_y[BS * COUT * LEN];    // conv output (64 MB)
__device__ __half g_xh[BS * CIN * LEN];    // fp16 scaled x (32 MB)
__device__ __half g_wh[3 * COUT * CIN];    // fp16 conv_w, [kk][o][i]

struct Filt { float up[17]; float dn[17]; };

// ---------------- K1: cond[b,c] (warp per (c,b)) ---------------------------
__global__ void cond_kernel(const float* __restrict__ w,
                            const float* __restrict__ aw,
                            const float* __restrict__ ab) {
    int gw = blockIdx.x * 8 + (threadIdx.x >> 5);  // 8192 warps = (c,b)
    int lane = threadIdx.x & 31;
    int c = gw & (CIN - 1);
    int b = gw >> 9;
    float acc = 0.f;
#pragma unroll
    for (int t = 0; t < 16; t++)
        acc = fmaf(aw[c * WDIM + lane + 32 * t], w[b * WDIM + lane + 32 * t], acc);
#pragma unroll
    for (int s = 16; s; s >>= 1) acc += __shfl_xor_sync(0xffffffffu, acc, s);
    if (lane == 0) g_cond[b * CIN + c] = acc + ab[c];
}

// ---------------- K2: inv_s ------------------------------------------------
__global__ void reduce_cond_kernel() {
    __shared__ float sm[256];
    float s = 0.f;
    for (int i = threadIdx.x; i < BS * CIN; i += 256) {
        float v = g_cond[i];
        s = fmaf(v, v, s);
    }
    sm[threadIdx.x] = s;
    __syncthreads();
    for (int off = 128; off; off >>= 1) {
        if (threadIdx.x < off) sm[threadIdx.x] += sm[threadIdx.x + off];
        __syncthreads();
    }
    if (threadIdx.x == 0) g_inv_s = rsqrtf(sm[0] / (float)(BS * CIN));
}

// ---------------- K3: g_sx = cond * inv_s * rsqrt(norm_ema) ----------------
__global__ void scale_s_kernel(const float* __restrict__ norm_ema) {
    int idx = blockIdx.x * blockDim.x + threadIdx.x;
    if (idx >= BS * CIN) return;
    g_sx[idx] = g_cond[idx] * g_inv_s * rsqrtf(norm_ema[0]);
}

// ---------------- K4: fused weight stats + demod scale ---------------------
__global__ void __launch_bounds__(128)
wdemod_kernel(const float* __restrict__ cw) {
    int o = blockIdx.x;
    int tid = threadIdx.x;
    __shared__ float red[128];
    __shared__ float sm2[16 * 128];
    __shared__ float s_invw;

    float w2[4];
    float sumw2 = 0.f;
#pragma unroll
    for (int j = 0; j < 4; j++) {
        int i = tid * 4 + j;
        const float* p = cw + (size_t)o * (CIN * 3) + i * 3;
        w2[j] = p[0] * p[0] + p[1] * p[1] + p[2] * p[2];
        sumw2 += w2[j];
    }
    red[tid] = sumw2;
    __syncthreads();
    for (int off = 64; off; off >>= 1) {
        if (tid < off) red[tid] += red[tid + off];
        __syncthreads();
    }
    if (tid == 0) s_invw = rsqrtf(red[0] / (float)(CIN * 3));
    __syncthreads();
    float invw = s_invw;

    float acc[16];
#pragma unroll
    for (int b = 0; b < 16; b++) acc[b] = 0.f;
#pragma unroll
    for (int j = 0; j < 4; j++) {
        int i = tid * 4 + j;
#pragma unroll
        for (int b = 0; b < 16; b++) {
            float cv = g_cond[b * CIN + i];
            acc[b] = fmaf(w2[j], cv * cv, acc[b]);
        }
    }
#pragma unroll
    for (int b = 0; b < 16; b++) sm2[b * 128 + tid] = acc[b];
    __syncthreads();
    for (int off = 64; off; off >>= 1) {
        for (int b = (tid >> 6); b < 16; b += 2) {
            int t = tid & 63;
            if (t < off) sm2[b * 128 + t] += sm2[b * 128 + t + off];
        }
        __syncthreads();
    }
    if (tid < 16) {
        float inv_s = g_inv_s;
        float f = invw * invw * inv_s * inv_s;
        g_scale[tid * COUT + o] = rsqrtf(f * sm2[tid * 128] + 1e-8f) * invw;
    }
}

// ---------------- K5a: weights -> fp16 [kk][o][i] --------------------------
__global__ void split_w_kernel(const float* __restrict__ cw) {
    int idx = blockIdx.x * blockDim.x + threadIdx.x;
    if (idx >= 3 * COUT * CIN) return;
    int i  = idx & (CIN - 1);
    int o  = (idx >> 9) & (COUT - 1);
    int kk = idx >> 18;
    g_wh[idx] = __float2half_rn(cw[(size_t)(o * CIN + i) * 3 + kk]);
}

// ---------------- K5b: scaled x -> fp16 ------------------------------------
__global__ void split_x_kernel(const float* __restrict__ x) {
    int idx4 = blockIdx.x * blockDim.x + threadIdx.x;   // quad index
    if (idx4 >= (BS * CIN * LEN) / 4) return;
    int row = idx4 >> 9;                                 // b*CIN + c
    float sc = g_sx[row];
    float4 v = ((const float4*)x)[idx4];
    uint32_t p0 = (uint32_t)__half_as_ushort(__float2half_rn(v.x * sc)) |
                  ((uint32_t)__half_as_ushort(__float2half_rn(v.y * sc)) << 16);
    uint32_t p1 = (uint32_t)__half_as_ushort(__float2half_rn(v.z * sc)) |
                  ((uint32_t)__half_as_ushort(__float2half_rn(v.w * sc)) << 16);
    ((uint2*)g_xh)[idx4] = make_uint2(p0, p1);
}

// ---------------- K6: FP16 modulated conv via mma.sync ---------------------
// Block tile: 128 o x 128 l, one batch. 8 warps (wm 0..3 x wn 0..1),
// warp tile 32 o x 64 l = 2 m16 x 8 n8 fragments.
// K chunk: CI=32 channels = 2 k16 tiles per tap; taps via B row shift.
#define BO   128
#define BLT  128
#define CI   32
#define XPAD 40                      // halves per smem row (20 words; conflict-free)
#define XROWS (BLT + 2)
#define WROWS (3 * BO)

__device__ __forceinline__ void mma16816h(float* c, const uint32_t a[4],
                                          uint32_t b0, uint32_t b1) {
    asm volatile(
        "mma.sync.aligned.m16n8k16.row.col.f32.f16.f16.f32 "
        "{%0,%1,%2,%3}, {%4,%5,%6,%7}, {%8,%9}, {%0,%1,%2,%3};"
        : "+f"(c[0]), "+f"(c[1]), "+f"(c[2]), "+f"(c[3])
        : "r"(a[0]), "r"(a[1]), "r"(a[2]), "r"(a[3]), "r"(b0), "r"(b1));
}

__global__ void __launch_bounds__(256)
conv_mma_kernel(const float* __restrict__ conv_b) {
    __shared__ unsigned short xsm[XROWS * XPAD];   // 10400 B
    __shared__ unsigned short wsm[WROWS * XPAD];   // 30720 B

    int tid  = threadIdx.x;
    int warp = tid >> 5;
    int lane = tid & 31;
    int grp  = lane >> 2;
    int tig  = lane & 3;
    int wm   = warp >> 1;   // 0..3
    int wn   = warp & 1;    // 0..1

    int l0 = blockIdx.x * BLT;
    int o0 = blockIdx.y * BO;
    int b  = blockIdx.z;

    float acc[2][8][4];
#pragma unroll
    for (int mt = 0; mt < 2; mt++)
#pragma unroll
        for (int nt = 0; nt < 8; nt++)
#pragma unroll
            for (int r = 0; r < 4; r++) acc[mt][nt][r] = 0.f;

    const __half* xb = g_xh + (size_t)b * CIN * LEN;

    for (int ic = 0; ic < CIN / CI; ic++) {
        int i0 = ic * CI;
        // ---- stage x: xsm[n][j] = x_h[i0+j][l0-1+n], j=0..31 ----
        for (int idx = tid; idx < CI * XROWS; idx += 256) {
            int j = idx / XROWS;
            int n = idx - j * XROWS;
            int gl = l0 - 1 + n;
            unsigned short hv = 0;
            if (gl >= 0 && gl < LEN)
                hv = __half_as_ushort(xb[(i0 + j) * LEN + gl]);
            xsm[n * XPAD + j] = hv;
        }
        // ---- stage w: wsm[kk*BO+o][j] (uint32 pairs along j) ----
        for (int idx = tid; idx < (3 * BO * CI) / 2; idx += 256) {
            int j2 = idx & 15;             // pair index 0..15
            int rest = idx >> 4;
            int o  = rest & (BO - 1);
            int kk = rest >> 7;
            uint32_t v = *(const uint32_t*)&g_wh[((kk * COUT) + o0 + o) * CIN
                                                 + i0 + 2 * j2];
            *(uint32_t*)&wsm[(kk * BO + o) * XPAD + 2 * j2] = v;
        }
        __syncthreads();

#pragma unroll
        for (int kk = 0; kk < 3; kk++) {
#pragma unroll
            for (int k16 = 0; k16 < 2; k16++) {
                int col = k16 * 16 + 2 * tig;
                uint32_t a[2][4];
#pragma unroll
                for (int mt = 0; mt < 2; mt++) {
                    const unsigned short* wp =
                        wsm + (kk * BO + wm * 32 + mt * 16 + grp) * XPAD + col;
                    a[mt][0] = *(const uint32_t*)(wp);
                    a[mt][1] = *(const uint32_t*)(wp + 8 * XPAD);
                    a[mt][2] = *(const uint32_t*)(wp + 8);
                    a[mt][3] = *(const uint32_t*)(wp + 8 * XPAD + 8);
                }
#pragma unroll
                for (int nt = 0; nt < 8; nt++) {
                    const unsigned short* xp =
                        xsm + (wn * 64 + nt * 8 + grp + kk) * XPAD + col;
                    uint32_t b0 = *(const uint32_t*)(xp);
                    uint32_t b1 = *(const uint32_t*)(xp + 8);
                    mma16816h(acc[0][nt], a[0], b0, b1);
                    mma16816h(acc[1][nt], a[1], b0, b1);
                }
            }
        }
        __syncthreads();
    }

    // ---- epilogue: per-o demod scale + bias -> g_y ----
#pragma unroll
    for (int mt = 0; mt < 2; mt++) {
        int oA = o0 + wm * 32 + mt * 16 + grp;
        int oB = oA + 8;
        float scA = g_scale[b * COUT + oA], bbA = conv_b[oA];
        float scB = g_scale[b * COUT + oB], bbB = conv_b[oB];
#pragma unroll
        for (int nt = 0; nt < 8; nt++) {
            int l = l0 + wn * 64 + nt * 8 + 2 * tig;
            float2 vA = make_float2(fmaf(acc[mt][nt][0], scA, bbA),
                                    fmaf(acc[mt][nt][1], scA, bbA));
            float2 vB = make_float2(fmaf(acc[mt][nt][2], scB, bbB),
                                    fmaf(acc[mt][nt][3], scB, bbB));
            *(float2*)&g_y[((size_t)(b * COUT + oA)) * LEN + l] = vA;
            *(float2*)&g_y[((size_t)(b * COUT + oB)) * LEN + l] = vB;
        }
    }
}

// ---------------- K7: fused up-LPF -> lrelu*sqrt2 -> down-LPF -> ::2 -------
__global__ void __launch_bounds__(256)
resample_kernel(float* __restrict__ out, Filt F) {
    __shared__ float ysm[LEN + 16];
    __shared__ float usm[2 * LEN + 16];
    int bc = blockIdx.x;
    const float* yrow = g_y + (size_t)bc * LEN;
    int t = threadIdx.x;

    if (t < 8) {
        ysm[t] = 0.f; ysm[LEN + 8 + t] = 0.f;
        usm[t] = 0.f; usm[2 * LEN + 8 + t] = 0.f;
    }
    for (int i = t; i < LEN; i += 256) ysm[8 + i] = yrow[i];
    __syncthreads();

    const float s2 = 1.41421356237f;
    for (int q = t; q < LEN; q += 256) {
        float ue = 0.f;
#pragma unroll
        for (int p = 0; p < 9; p++) ue = fmaf(F.up[2 * p], ysm[q + 4 + p], ue);
        float uo = 0.f;
#pragma unroll
        for (int p = 0; p < 8; p++) uo = fmaf(F.up[2 * p + 1], ysm[q + 5 + p], uo);
        usm[8 + 2 * q]     = (ue > 0.f ? ue : 0.1f * ue) * s2;
        usm[8 + 2 * q + 1] = (uo > 0.f ? uo : 0.1f * uo) * s2;
    }
    __syncthreads();

    float* orow = out + (size_t)bc * LEN;
    for (int tt = t; tt < LEN; tt += 256) {
        float z = 0.f;
#pragma unroll
        for (int k = 0; k < 17; k++) z = fmaf(F.dn[k], usm[2 * tt + k], z);
        orow[tt] = z;
    }
}

// ---------------- host: Kaiser-sinc filter ---------------------------------
static double bessel_i0(double x) {
    double s = 1.0, term = 1.0;
    for (int k = 1; k < 64; k++) {
        double h = x / (2.0 * k);
        term *= h * h;
        s += term;
        if (term < 1e-18 * s) break;
    }
    return s;
}
static void make_filter(float* f) {
    const double PI = 3.14159265358979323846;
    double i0b = bessel_i0(2.5);
    for (int i = 0; i < 17; i++) {
        int n = i - 8;
        float fv;
        if (n == 0) fv = 0.5f;
        else fv = (float)sin(0.5 * PI * (double)n) / ((float)(PI * (double)n) + 1e-8f);
        double r = (double)n / 8.0;
        double win = bessel_i0(2.5 * sqrt(1.0 - r * r)) / i0b;
        f[i] = (float)win * fv;
    }
}

// ---------------- launcher -------------------------------------------------
extern "C" void kernel_launch(void* const* d_in, const int* in_sizes, int n_in,
                              void* d_out, int out_size) {
    const float* x        = (const float*)d_in[0];
    const float* w        = (const float*)d_in[1];
    const float* affine_w = (const float*)d_in[2];
    const float* affine_b = (const float*)d_in[3];
    const float* conv_w   = (const float*)d_in[4];
    const float* conv_b   = (const float*)d_in[5];
    const float* norm_ema = (const float*)d_in[6];
    float* out = (float*)d_out;

    Filt F;
    make_filter(F.up);
    make_filter(F.dn);

    cond_kernel<<<1024, 256>>>(w, affine_w, affine_b);
    reduce_cond_kernel<<<1, 256>>>();
    scale_s_kernel<<<32, 256>>>(norm_ema);
    wdemod_kernel<<<COUT, 128>>>(conv_w);
    split_w_kernel<<<(3 * COUT * CIN + 255) / 256, 256>>>(conv_w);
    split_x_kernel<<<(BS * CIN * LEN / 4 + 255) / 256, 256>>>(x);

    dim3 cgrid(LEN / BLT, COUT / BO, BS);
    conv_mma_kernel<<<cgrid, 256>>>(conv_b);

    resample_kernel<<<BS * COUT, 256>>>(out, F);
}

// round 7
// speedup vs baseline: 2.5663x; 1.1867x over previous
#include <cuda_runtime.h>
#include <cuda_fp16.h>
#include <math.h>
#include <stdint.h>

// ---------------------------------------------------------------------------
// bs=16, c_in=c_out=512, w_dim=512, L=2048, k=3, UP=DOWN=2, 17-tap Kaiser LPF
// Conv: pure FP16 implicit GEMM, mma.sync.m16n8k16 + ldmatrix fragment loads.
// y stored fp16; resample register-blocked with even/odd upsample planes.
// ---------------------------------------------------------------------------

#define BS   16
#define CIN  512
#define COUT 512
#define LEN  2048
#define WDIM 512

// ---------------- device scratch -------------------------------------------
__device__ float  g_cond[BS * CIN];
__device__ float  g_sx[BS * CIN];          // cond * inv_s * rsqrt(norm_ema)
__device__ float  g_scale[BS * COUT];      // d[b,o] * invw[o]
__device__ float  g_inv_s;
__device__ __half g_yh[BS * COUT * LEN];   // conv output fp16 (32 MB)
__device__ __half g_xh[BS * CIN * LEN];    // fp16 scaled x (32 MB)
__device__ __half g_wh[3 * COUT * CIN];    // fp16 conv_w, [kk][o][i]

struct Filt { float up[17]; float dn[17]; };

// ---------------- K1: cond[b,c] (warp per (c,b)) ---------------------------
__global__ void cond_kernel(const float* __restrict__ w,
                            const float* __restrict__ aw,
                            const float* __restrict__ ab) {
    int gw = blockIdx.x * 8 + (threadIdx.x >> 5);
    int lane = threadIdx.x & 31;
    int c = gw & (CIN - 1);
    int b = gw >> 9;
    float acc = 0.f;
#pragma unroll
    for (int t = 0; t < 16; t++)
        acc = fmaf(aw[c * WDIM + lane + 32 * t], w[b * WDIM + lane + 32 * t], acc);
#pragma unroll
    for (int s = 16; s; s >>= 1) acc += __shfl_xor_sync(0xffffffffu, acc, s);
    if (lane == 0) g_cond[b * CIN + c] = acc + ab[c];
}

// ---------------- K2: inv_s ------------------------------------------------
__global__ void reduce_cond_kernel() {
    __shared__ float sm[256];
    float s = 0.f;
    for (int i = threadIdx.x; i < BS * CIN; i += 256) {
        float v = g_cond[i];
        s = fmaf(v, v, s);
    }
    sm[threadIdx.x] = s;
    __syncthreads();
    for (int off = 128; off; off >>= 1) {
        if (threadIdx.x < off) sm[threadIdx.x] += sm[threadIdx.x + off];
        __syncthreads();
    }
    if (threadIdx.x == 0) g_inv_s = rsqrtf(sm[0] / (float)(BS * CIN));
}

// ---------------- K3: g_sx = cond * inv_s * rsqrt(norm_ema) ----------------
__global__ void scale_s_kernel(const float* __restrict__ norm_ema) {
    int idx = blockIdx.x * blockDim.x + threadIdx.x;
    if (idx >= BS * CIN) return;
    g_sx[idx] = g_cond[idx] * g_inv_s * rsqrtf(norm_ema[0]);
}

// ---------------- K4: fused weight stats + demod scale ---------------------
__global__ void __launch_bounds__(128)
wdemod_kernel(const float* __restrict__ cw) {
    int o = blockIdx.x;
    int tid = threadIdx.x;
    __shared__ float red[128];
    __shared__ float sm2[16 * 128];
    __shared__ float s_invw;

    float w2[4];
    float sumw2 = 0.f;
#pragma unroll
    for (int j = 0; j < 4; j++) {
        int i = tid * 4 + j;
        const float* p = cw + (size_t)o * (CIN * 3) + i * 3;
        w2[j] = p[0] * p[0] + p[1] * p[1] + p[2] * p[2];
        sumw2 += w2[j];
    }
    red[tid] = sumw2;
    __syncthreads();
    for (int off = 64; off; off >>= 1) {
        if (tid < off) red[tid] += red[tid + off];
        __syncthreads();
    }
    if (tid == 0) s_invw = rsqrtf(red[0] / (float)(CIN * 3));
    __syncthreads();
    float invw = s_invw;

    float acc[16];
#pragma unroll
    for (int b = 0; b < 16; b++) acc[b] = 0.f;
#pragma unroll
    for (int j = 0; j < 4; j++) {
        int i = tid * 4 + j;
#pragma unroll
        for (int b = 0; b < 16; b++) {
            float cv = g_cond[b * CIN + i];
            acc[b] = fmaf(w2[j], cv * cv, acc[b]);
        }
    }
#pragma unroll
    for (int b = 0; b < 16; b++) sm2[b * 128 + tid] = acc[b];
    __syncthreads();
    for (int off = 64; off; off >>= 1) {
        for (int b = (tid >> 6); b < 16; b += 2) {
            int t = tid & 63;
            if (t < off) sm2[b * 128 + t] += sm2[b * 128 + t + off];
        }
        __syncthreads();
    }
    if (tid < 16) {
        float inv_s = g_inv_s;
        float f = invw * invw * inv_s * inv_s;
        g_scale[tid * COUT + o] = rsqrtf(f * sm2[tid * 128] + 1e-8f) * invw;
    }
}

// ---------------- K5a: weights -> fp16 [kk][o][i] --------------------------
__global__ void split_w_kernel(const float* __restrict__ cw) {
    int idx = blockIdx.x * blockDim.x + threadIdx.x;
    if (idx >= 3 * COUT * CIN) return;
    int i  = idx & (CIN - 1);
    int o  = (idx >> 9) & (COUT - 1);
    int kk = idx >> 18;
    g_wh[idx] = __float2half_rn(cw[(size_t)(o * CIN + i) * 3 + kk]);
}

// ---------------- K5b: scaled x -> fp16 ------------------------------------
__global__ void split_x_kernel(const float* __restrict__ x) {
    int idx4 = blockIdx.x * blockDim.x + threadIdx.x;
    if (idx4 >= (BS * CIN * LEN) / 4) return;
    int row = idx4 >> 9;
    float sc = g_sx[row];
    float4 v = ((const float4*)x)[idx4];
    uint32_t p0 = (uint32_t)__half_as_ushort(__float2half_rn(v.x * sc)) |
                  ((uint32_t)__half_as_ushort(__float2half_rn(v.y * sc)) << 16);
    uint32_t p1 = (uint32_t)__half_as_ushort(__float2half_rn(v.z * sc)) |
                  ((uint32_t)__half_as_ushort(__float2half_rn(v.w * sc)) << 16);
    ((uint2*)g_xh)[idx4] = make_uint2(p0, p1);
}

// ---------------- K6: FP16 conv via mma.sync + ldmatrix --------------------
// Block tile: 128 o x 256 l, one batch; 512 threads = 16 warps (wm0..3 x wn0..3)
// Warp tile 32 o x 64 l = 2 m16 x 8 n8 fragments. K chunk CI=32 channels.
// xsm [n=258 rows][XPAD], wsm [3*128 rows][XPAD]; XPAD=40 halves (bank-clean).
#define BO   128
#define BLT  256
#define CI   32
#define XPAD 40
#define XROWS (BLT + 2)
#define WROWS (3 * BO)
#define CONV_SMEM ((XROWS + WROWS) * XPAD * 2)

__device__ __forceinline__ uint32_t smem_u32(const void* p) {
    uint32_t a;
    asm("{ .reg .u64 t; cvta.to.shared.u64 t, %1; cvt.u32.u64 %0, t; }"
        : "=r"(a) : "l"(p));
    return a;
}
__device__ __forceinline__ void ldsm4(uint32_t* r, uint32_t addr) {
    asm volatile("ldmatrix.sync.aligned.m8n8.x4.shared.b16 {%0,%1,%2,%3}, [%4];"
        : "=r"(r[0]), "=r"(r[1]), "=r"(r[2]), "=r"(r[3]) : "r"(addr));
}
__device__ __forceinline__ void mma16816h(float* c, const uint32_t a[4],
                                          uint32_t b0, uint32_t b1) {
    asm volatile(
        "mma.sync.aligned.m16n8k16.row.col.f32.f16.f16.f32 "
        "{%0,%1,%2,%3}, {%4,%5,%6,%7}, {%8,%9}, {%0,%1,%2,%3};"
        : "+f"(c[0]), "+f"(c[1]), "+f"(c[2]), "+f"(c[3])
        : "r"(a[0]), "r"(a[1]), "r"(a[2]), "r"(a[3]), "r"(b0), "r"(b1));
}

__global__ void __launch_bounds__(512, 1)
conv_mma_kernel(const float* __restrict__ conv_b) {
    extern __shared__ unsigned short smem[];
    unsigned short* xsm = smem;                  // [XROWS][XPAD]
    unsigned short* wsm = smem + XROWS * XPAD;   // [WROWS][XPAD]
    uint32_t xsm_b = smem_u32(xsm);
    uint32_t wsm_b = smem_u32(wsm);

    int tid  = threadIdx.x;
    int warp = tid >> 5;
    int lane = tid & 31;
    int grp  = lane >> 2;
    int tig  = lane & 3;
    int wm   = warp >> 2;   // 0..3
    int wn   = warp & 3;    // 0..3

    int l0 = blockIdx.x * BLT;
    int o0 = blockIdx.y * BO;
    int b  = blockIdx.z;

    float acc[2][8][4];
#pragma unroll
    for (int mt = 0; mt < 2; mt++)
#pragma unroll
        for (int nt = 0; nt < 8; nt++)
#pragma unroll
            for (int r = 0; r < 4; r++) acc[mt][nt][r] = 0.f;

    const __half* xb = g_xh + (size_t)b * CIN * LEN;

    // precomputed ldmatrix lane sub-offsets
    int a_row_l = lane & 15;
    int a_col_l = ((lane >> 4) & 1) << 3;
    int b_row_l = (((lane >> 4) & 1) << 3) + (lane & 7);
    int b_col_l = ((lane >> 3) & 1) << 3;

    for (int ic = 0; ic < CIN / CI; ic++) {
        int i0 = ic * CI;
        // ---- stage x: xsm[n][j] = x[i0+j][l0-1+n] ----
        for (int idx = tid; idx < CI * XROWS; idx += 512) {
            int j = idx / XROWS;
            int n = idx - j * XROWS;
            int gl = l0 - 1 + n;
            unsigned short hv = 0;
            if (gl >= 0 && gl < LEN)
                hv = __half_as_ushort(xb[(i0 + j) * LEN + gl]);
            xsm[n * XPAD + j] = hv;
        }
        // ---- stage w: wsm[kk*BO+o][j] ----
        for (int idx = tid; idx < (3 * BO * CI) / 2; idx += 512) {
            int j2 = idx & 15;
            int rest = idx >> 4;
            int o  = rest & (BO - 1);
            int kk = rest >> 7;
            uint32_t v = *(const uint32_t*)&g_wh[((kk * COUT) + o0 + o) * CIN
                                                 + i0 + 2 * j2];
            *(uint32_t*)&wsm[(kk * BO + o) * XPAD + 2 * j2] = v;
        }
        __syncthreads();

#pragma unroll
        for (int kk = 0; kk < 3; kk++) {
#pragma unroll
            for (int k16 = 0; k16 < 2; k16++) {
                uint32_t a[2][4];
#pragma unroll
                for (int mt = 0; mt < 2; mt++) {
                    int row = kk * BO + wm * 32 + mt * 16 + a_row_l;
                    int col = k16 * 16 + a_col_l;
                    ldsm4(a[mt], wsm_b + (uint32_t)(row * XPAD + col) * 2u);
                }
                uint32_t bb[4][4];
#pragma unroll
                for (int ntp = 0; ntp < 4; ntp++) {
                    int row = wn * 64 + ntp * 16 + b_row_l + kk;
                    int col = k16 * 16 + b_col_l;
                    ldsm4(bb[ntp], xsm_b + (uint32_t)(row * XPAD + col) * 2u);
                }
#pragma unroll
                for (int ntp = 0; ntp < 4; ntp++) {
#pragma unroll
                    for (int h = 0; h < 2; h++) {
                        mma16816h(acc[0][2 * ntp + h], a[0], bb[ntp][2 * h],
                                  bb[ntp][2 * h + 1]);
                        mma16816h(acc[1][2 * ntp + h], a[1], bb[ntp][2 * h],
                                  bb[ntp][2 * h + 1]);
                    }
                }
            }
        }
        __syncthreads();
    }

    // ---- epilogue: demod scale + bias -> fp16 g_yh ----
#pragma unroll
    for (int mt = 0; mt < 2; mt++) {
        int oA = o0 + wm * 32 + mt * 16 + grp;
        int oB = oA + 8;
        float scA = g_scale[b * COUT + oA], bbA = conv_b[oA];
        float scB = g_scale[b * COUT + oB], bbB = conv_b[oB];
#pragma unroll
        for (int nt = 0; nt < 8; nt++) {
            int l = l0 + wn * 64 + nt * 8 + 2 * tig;
            __half2 vA = __floats2half2_rn(fmaf(acc[mt][nt][0], scA, bbA),
                                           fmaf(acc[mt][nt][1], scA, bbA));
            __half2 vB = __floats2half2_rn(fmaf(acc[mt][nt][2], scB, bbB),
                                           fmaf(acc[mt][nt][3], scB, bbB));
            *(__half2*)&g_yh[((size_t)(b * COUT + oA)) * LEN + l] = vA;
            *(__half2*)&g_yh[((size_t)(b * COUT + oB)) * LEN + l] = vB;
        }
    }
}

// ---------------- K7: resample, register-blocked ---------------------------
// up-LPF -> lrelu*sqrt2 (even/odd planes) -> down-LPF stride-1 -> out
__global__ void __launch_bounds__(256)
resample_kernel(float* __restrict__ out, Filt F) {
    __shared__ float ysm[2064];            // [8 pad | 2048 | 8 pad]
    __shared__ float ue[2064], uo[2064];   // even/odd upsampled+lrelu planes
    int bc = blockIdx.x;
    int t  = threadIdx.x;
    const __half* yrow = g_yh + (size_t)bc * LEN;

    if (t < 8) {
        ysm[t] = 0.f; ysm[2056 + t] = 0.f;
        ue[t]  = 0.f; ue[2056 + t]  = 0.f;
        uo[t]  = 0.f; uo[2056 + t]  = 0.f;
    }
    {   // load 8 halves -> 8 floats
        uint4 v = ((const uint4*)yrow)[t];
        __half2* hp = (__half2*)&v;
        float2 p0 = __half22float2(hp[0]);
        float2 p1 = __half22float2(hp[1]);
        float2 p2 = __half22float2(hp[2]);
        float2 p3 = __half22float2(hp[3]);
        *(float4*)&ysm[8 + 8 * t]     = make_float4(p0.x, p0.y, p1.x, p1.y);
        *(float4*)&ysm[8 + 8 * t + 4] = make_float4(p2.x, p2.y, p3.x, p3.y);
    }
    __syncthreads();

    const float s2 = 1.41421356237f;
    {   // up + lrelu: thread computes q = 8t..8t+7
        float w[16];
        *(float4*)&w[0]  = *(const float4*)&ysm[8 * t + 4];
        *(float4*)&w[4]  = *(const float4*)&ysm[8 * t + 8];
        *(float4*)&w[8]  = *(const float4*)&ysm[8 * t + 12];
        *(float4*)&w[12] = *(const float4*)&ysm[8 * t + 16];
        float e[8], o8[8];
#pragma unroll
        for (int p = 0; p < 8; p++) {
            float ev = 0.f, ov = 0.f;
#pragma unroll
            for (int j = 0; j < 9; j++) ev = fmaf(F.up[2 * j], w[p + j], ev);
#pragma unroll
            for (int j = 0; j < 8; j++) ov = fmaf(F.up[2 * j + 1], w[p + 1 + j], ov);
            e[p]  = (ev > 0.f ? ev : 0.1f * ev) * s2;
            o8[p] = (ov > 0.f ? ov : 0.1f * ov) * s2;
        }
        *(float4*)&ue[8 + 8 * t]     = make_float4(e[0], e[1], e[2], e[3]);
        *(float4*)&ue[8 + 8 * t + 4] = make_float4(e[4], e[5], e[6], e[7]);
        *(float4*)&uo[8 + 8 * t]     = make_float4(o8[0], o8[1], o8[2], o8[3]);
        *(float4*)&uo[8 + 8 * t + 4] = make_float4(o8[4], o8[5], o8[6], o8[7]);
    }
    __syncthreads();

    {   // down: thread computes tt = 8t..8t+7
        float we[16], wo[16];
        *(float4*)&we[0]  = *(const float4*)&ue[8 * t + 4];
        *(float4*)&we[4]  = *(const float4*)&ue[8 * t + 8];
        *(float4*)&we[8]  = *(const float4*)&ue[8 * t + 12];
        *(float4*)&we[12] = *(const float4*)&ue[8 * t + 16];
        *(float4*)&wo[0]  = *(const float4*)&uo[8 * t + 4];
        *(float4*)&wo[4]  = *(const float4*)&uo[8 * t + 8];
        *(float4*)&wo[8]  = *(const float4*)&uo[8 * t + 12];
        *(float4*)&wo[12] = *(const float4*)&uo[8 * t + 16];
        float z[8];
#pragma unroll
        for (int p = 0; p < 8; p++) {
            float zv = 0.f;
#pragma unroll
            for (int j = 0; j < 9; j++) zv = fmaf(F.dn[2 * j], we[p + j], zv);
#pragma unroll
            for (int j = 0; j < 8; j++) zv = fmaf(F.dn[2 * j + 1], wo[p + j], zv);
            z[p] = zv;
        }
        float* orow = out + (size_t)bc * LEN + 8 * t;
        *(float4*)&orow[0] = make_float4(z[0], z[1], z[2], z[3]);
        *(float4*)&orow[4] = make_float4(z[4], z[5], z[6], z[7]);
    }
}

// ---------------- host: Kaiser-sinc filter ---------------------------------
static double bessel_i0(double x) {
    double s = 1.0, term = 1.0;
    for (int k = 1; k < 64; k++) {
        double h = x / (2.0 * k);
        term *= h * h;
        s += term;
        if (term < 1e-18 * s) break;
    }
    return s;
}
static void make_filter(float* f) {
    const double PI = 3.14159265358979323846;
    double i0b = bessel_i0(2.5);
    for (int i = 0; i < 17; i++) {
        int n = i - 8;
        float fv;
        if (n == 0) fv = 0.5f;
        else fv = (float)sin(0.5 * PI * (double)n) / ((float)(PI * (double)n) + 1e-8f);
        double r = (double)n / 8.0;
        double win = bessel_i0(2.5 * sqrt(1.0 - r * r)) / i0b;
        f[i] = (float)win * fv;
    }
}

// ---------------- launcher -------------------------------------------------
extern "C" void kernel_launch(void* const* d_in, const int* in_sizes, int n_in,
                              void* d_out, int out_size) {
    const float* x        = (const float*)d_in[0];
    const float* w        = (const float*)d_in[1];
    const float* affine_w = (const float*)d_in[2];
    const float* affine_b = (const float*)d_in[3];
    const float* conv_w   = (const float*)d_in[4];
    const float* conv_b   = (const float*)d_in[5];
    const float* norm_ema = (const float*)d_in[6];
    float* out = (float*)d_out;

    Filt F;
    make_filter(F.up);
    make_filter(F.dn);

    cudaFuncSetAttribute(conv_mma_kernel,
                         cudaFuncAttributeMaxDynamicSharedMemorySize, CONV_SMEM);

    cond_kernel<<<1024, 256>>>(w, affine_w, affine_b);
    reduce_cond_kernel<<<1, 256>>>();
    scale_s_kernel<<<32, 256>>>(norm_ema);
    wdemod_kernel<<<COUT, 128>>>(conv_w);
    split_w_kernel<<<(3 * COUT * CIN + 255) / 256, 256>>>(conv_w);
    split_x_kernel<<<(BS * CIN * LEN / 4 + 255) / 256, 256>>>(x);

    dim3 cgrid(LEN / BLT, COUT / BO, BS);
    conv_mma_kernel<<<cgrid, 512, CONV_SMEM>>>(conv_b);

    resample_kernel<<<BS * COUT, 256>>>(out, F);
}

// round 8
// speedup vs baseline: 3.6989x; 1.4413x over previous
#include <cuda_runtime.h>
#include <cuda_fp16.h>
#include <math.h>
#include <stdint.h>

// ---------------------------------------------------------------------------
// bs=16, c_in=c_out=512, w_dim=512, L=2048, k=3, UP=DOWN=2, 17-tap Kaiser LPF
// Conv: FP16 implicit GEMM, mma.sync + ldmatrix, cp.async double-buffered.
// x pre-transposed to [b][l][ch] fp16 so tile rows are contiguous in gmem.
// ---------------------------------------------------------------------------

#define BS   16
#define CIN  512
#define COUT 512
#define LEN  2048
#define WDIM 512

// ---------------- device scratch -------------------------------------------
__device__ float  g_cond[BS * CIN];
__device__ float  g_sx[BS * CIN];          // cond * inv_s * rsqrt(norm_ema)
__device__ float  g_scale[BS * COUT];      // d[b,o] * invw[o]
__device__ float  g_inv_s;
__device__ __half g_yh[BS * COUT * LEN];   // conv output fp16 (32 MB)
__device__ __half g_xt[BS * LEN * CIN];    // fp16 scaled x, transposed (32 MB)
__device__ __half g_wh[3 * COUT * CIN];    // fp16 conv_w, [kk][o][i]

struct Filt { float up[17]; float dn[17]; };

// ---------------- K1: cond[b,c] (warp per (c,b)) ---------------------------
__global__ void cond_kernel(const float* __restrict__ w,
                            const float* __restrict__ aw,
                            const float* __restrict__ ab) {
    int gw = blockIdx.x * 8 + (threadIdx.x >> 5);
    int lane = threadIdx.x & 31;
    int c = gw & (CIN - 1);
    int b = gw >> 9;
    float acc = 0.f;
#pragma unroll
    for (int t = 0; t < 16; t++)
        acc = fmaf(aw[c * WDIM + lane + 32 * t], w[b * WDIM + lane + 32 * t], acc);
#pragma unroll
    for (int s = 16; s; s >>= 1) acc += __shfl_xor_sync(0xffffffffu, acc, s);
    if (lane == 0) g_cond[b * CIN + c] = acc + ab[c];
}

// ---------------- K2: inv_s ------------------------------------------------
__global__ void reduce_cond_kernel() {
    __shared__ float sm[256];
    float s = 0.f;
    for (int i = threadIdx.x; i < BS * CIN; i += 256) {
        float v = g_cond[i];
        s = fmaf(v, v, s);
    }
    sm[threadIdx.x] = s;
    __syncthreads();
    for (int off = 128; off; off >>= 1) {
        if (threadIdx.x < off) sm[threadIdx.x] += sm[threadIdx.x + off];
        __syncthreads();
    }
    if (threadIdx.x == 0) g_inv_s = rsqrtf(sm[0] / (float)(BS * CIN));
}

// ---------------- K3: g_sx -------------------------------------------------
__global__ void scale_s_kernel(const float* __restrict__ norm_ema) {
    int idx = blockIdx.x * blockDim.x + threadIdx.x;
    if (idx >= BS * CIN) return;
    g_sx[idx] = g_cond[idx] * g_inv_s * rsqrtf(norm_ema[0]);
}

// ---------------- K4: fused weight stats + demod scale ---------------------
__global__ void __launch_bounds__(128)
wdemod_kernel(const float* __restrict__ cw) {
    int o = blockIdx.x;
    int tid = threadIdx.x;
    __shared__ float red[128];
    __shared__ float sm2[16 * 128];
    __shared__ float s_invw;

    float w2[4];
    float sumw2 = 0.f;
#pragma unroll
    for (int j = 0; j < 4; j++) {
        int i = tid * 4 + j;
        const float* p = cw + (size_t)o * (CIN * 3) + i * 3;
        w2[j] = p[0] * p[0] + p[1] * p[1] + p[2] * p[2];
        sumw2 += w2[j];
    }
    red[tid] = sumw2;
    __syncthreads();
    for (int off = 64; off; off >>= 1) {
        if (tid < off) red[tid] += red[tid + off];
        __syncthreads();
    }
    if (tid == 0) s_invw = rsqrtf(red[0] / (float)(CIN * 3));
    __syncthreads();
    float invw = s_invw;

    float acc[16];
#pragma unroll
    for (int b = 0; b < 16; b++) acc[b] = 0.f;
#pragma unroll
    for (int j = 0; j < 4; j++) {
        int i = tid * 4 + j;
#pragma unroll
        for (int b = 0; b < 16; b++) {
            float cv = g_cond[b * CIN + i];
            acc[b] = fmaf(w2[j], cv * cv, acc[b]);
        }
    }
#pragma unroll
    for (int b = 0; b < 16; b++) sm2[b * 128 + tid] = acc[b];
    __syncthreads();
    for (int off = 64; off; off >>= 1) {
        for (int b = (tid >> 6); b < 16; b += 2) {
            int t = tid & 63;
            if (t < off) sm2[b * 128 + t] += sm2[b * 128 + t + off];
        }
        __syncthreads();
    }
    if (tid < 16) {
        float inv_s = g_inv_s;
        float f = invw * invw * inv_s * inv_s;
        g_scale[tid * COUT + o] = rsqrtf(f * sm2[tid * 128] + 1e-8f) * invw;
    }
}

// ---------------- K5a: weights -> fp16 [kk][o][i] --------------------------
__global__ void split_w_kernel(const float* __restrict__ cw) {
    int idx = blockIdx.x * blockDim.x + threadIdx.x;
    if (idx >= 3 * COUT * CIN) return;
    int i  = idx & (CIN - 1);
    int o  = (idx >> 9) & (COUT - 1);
    int kk = idx >> 18;
    g_wh[idx] = __float2half_rn(cw[(size_t)(o * CIN + i) * 3 + kk]);
}

// ---------------- K5b: transpose + scale x -> fp16 [b][l][ch] --------------
__global__ void __launch_bounds__(256)
transpose_x_kernel(const float* __restrict__ x) {
    __shared__ float tile[32][33];
    __shared__ float sc[32];
    int b  = blockIdx.z;
    int c0 = blockIdx.y * 32;
    int l0 = blockIdx.x * 32;
    int tx = threadIdx.x & 31;
    int ty = threadIdx.x >> 5;   // 0..7
    if (ty == 0) sc[tx] = g_sx[b * CIN + c0 + tx];
    __syncthreads();
#pragma unroll
    for (int cy = 0; cy < 4; cy++) {
        int ch = ty + 8 * cy;
        tile[ch][tx] = x[((size_t)(b * CIN + c0 + ch)) * LEN + l0 + tx] * sc[ch];
    }
    __syncthreads();
#pragma unroll
    for (int cy = 0; cy < 4; cy++) {
        int lr = ty + 8 * cy;
        g_xt[((size_t)(b * LEN + l0 + lr)) * CIN + c0 + tx] =
            __float2half_rn(tile[tx][lr]);
    }
}

// ---------------- K6: FP16 conv, cp.async 2-stage pipeline -----------------
// Block tile: 128 o x 256 l; 512 threads = 16 warps (wm0..3 x wn0..3).
// Warp tile 32 o x 64 l. K chunk CI=32 channels; smem rows XPAD=40 halves.
#define BO   128
#define BLT  256
#define CI   32
#define XPAD 40
#define XROWS (BLT + 2)          // 258
#define WROWS (3 * BO)           // 384
#define XBUF_B (XROWS * XPAD * 2)    // 20640
#define WBUF_B (WROWS * XPAD * 2)    // 30720
#define STAGE_B (XBUF_B + WBUF_B)    // 51360
#define CONV_SMEM (2 * STAGE_B)      // 102720

__device__ __forceinline__ uint32_t smem_u32(const void* p) {
    uint32_t a;
    asm("{ .reg .u64 t; cvta.to.shared.u64 t, %1; cvt.u32.u64 %0, t; }"
        : "=r"(a) : "l"(p));
    return a;
}
__device__ __forceinline__ void cp16(uint32_t dst, const void* src, uint32_t valid) {
    // ignore-src predicate: true => zero-fill dst
    asm volatile("{\n\t.reg .pred p;\n\tsetp.eq.u32 p, %2, 0;\n\t"
                 "cp.async.ca.shared.global [%0], [%1], 16, p;\n\t}"
                 :: "r"(dst), "l"(src), "r"(valid) : "memory");
}
__device__ __forceinline__ void cp_commit() {
    asm volatile("cp.async.commit_group;" ::: "memory");
}
template <int N>
__device__ __forceinline__ void cp_wait() {
    asm volatile("cp.async.wait_group %0;" :: "n"(N) : "memory");
}
__device__ __forceinline__ void ldsm4(uint32_t* r, uint32_t addr) {
    asm volatile("ldmatrix.sync.aligned.m8n8.x4.shared.b16 {%0,%1,%2,%3}, [%4];"
        : "=r"(r[0]), "=r"(r[1]), "=r"(r[2]), "=r"(r[3]) : "r"(addr));
}
__device__ __forceinline__ void mma16816h(float* c, const uint32_t a[4],
                                          uint32_t b0, uint32_t b1) {
    asm volatile(
        "mma.sync.aligned.m16n8k16.row.col.f32.f16.f16.f32 "
        "{%0,%1,%2,%3}, {%4,%5,%6,%7}, {%8,%9}, {%0,%1,%2,%3};"
        : "+f"(c[0]), "+f"(c[1]), "+f"(c[2]), "+f"(c[3])
        : "r"(a[0]), "r"(a[1]), "r"(a[2]), "r"(a[3]), "r"(b0), "r"(b1));
}

__global__ void __launch_bounds__(512, 1)
conv_mma_kernel(const float* __restrict__ conv_b) {
    extern __shared__ char smem[];
    uint32_t sbase = smem_u32(smem);

    int tid  = threadIdx.x;
    int warp = tid >> 5;
    int lane = tid & 31;
    int grp  = lane >> 2;
    int tig  = lane & 3;
    int wm   = warp >> 2;   // 0..3
    int wn   = warp & 3;    // 0..3

    int l0 = blockIdx.x * BLT;
    int o0 = blockIdx.y * BO;
    int b  = blockIdx.z;

    float acc[2][8][4];
#pragma unroll
    for (int mt = 0; mt < 2; mt++)
#pragma unroll
        for (int nt = 0; nt < 8; nt++)
#pragma unroll
            for (int r = 0; r < 4; r++) acc[mt][nt][r] = 0.f;

    const __half* xrow = g_xt + (size_t)b * LEN * CIN;

    // ldmatrix lane sub-offsets
    int a_row_l = lane & 15;
    int a_col_l = ((lane >> 4) & 1) << 3;
    int b_row_l = (((lane >> 4) & 1) << 3) + (lane & 7);
    int b_col_l = ((lane >> 3) & 1) << 3;

    // ---- staging: 2568 cp.async of 16B per chunk --------------------------
    auto stage = [&](int c, int s) {
        int i0 = c * CI;
        uint32_t xb = sbase + s * STAGE_B;
        uint32_t wb = xb + XBUF_B;
        for (int idx = tid; idx < XROWS * 4 + WROWS * 4; idx += 512) {
            if (idx < XROWS * 4) {
                int n = idx >> 2, q = idx & 3;
                int gl = l0 - 1 + n;
                cp16(xb + n * (XPAD * 2) + q * 16,
                     xrow + (size_t)gl * CIN + i0 + q * 8,
                     (uint32_t)(gl >= 0 && gl < LEN));
            } else {
                int r = (idx - XROWS * 4) >> 2, q = idx & 3;
                int kk = r >> 7, o = r & 127;
                cp16(wb + r * (XPAD * 2) + q * 16,
                     g_wh + ((size_t)(kk * COUT) + o0 + o) * CIN + i0 + q * 8,
                     1u);
            }
        }
        cp_commit();
    };

    auto compute = [&](int s) {
        uint32_t xsm_b = sbase + s * STAGE_B;
        uint32_t wsm_b = xsm_b + XBUF_B;
#pragma unroll
        for (int kk = 0; kk < 3; kk++) {
#pragma unroll
            for (int k16 = 0; k16 < 2; k16++) {
                uint32_t a[2][4];
#pragma unroll
                for (int mt = 0; mt < 2; mt++) {
                    int row = kk * BO + wm * 32 + mt * 16 + a_row_l;
                    int col = k16 * 16 + a_col_l;
                    ldsm4(a[mt], wsm_b + (uint32_t)(row * XPAD + col) * 2u);
                }
                uint32_t bb[4][4];
#pragma unroll
                for (int ntp = 0; ntp < 4; ntp++) {
                    int row = wn * 64 + ntp * 16 + b_row_l + kk;
                    int col = k16 * 16 + b_col_l;
                    ldsm4(bb[ntp], xsm_b + (uint32_t)(row * XPAD + col) * 2u);
                }
#pragma unroll
                for (int ntp = 0; ntp < 4; ntp++) {
#pragma unroll
                    for (int h = 0; h < 2; h++) {
                        mma16816h(acc[0][2 * ntp + h], a[0], bb[ntp][2 * h],
                                  bb[ntp][2 * h + 1]);
                        mma16816h(acc[1][2 * ntp + h], a[1], bb[ntp][2 * h],
                                  bb[ntp][2 * h + 1]);
                    }
                }
            }
        }
    };

    stage(0, 0);
    for (int c = 0; c < 16; c++) {
        if (c + 1 < 16) {
            stage(c + 1, (c + 1) & 1);
            cp_wait<1>();
        } else {
            cp_wait<0>();
        }
        __syncthreads();
        compute(c & 1);
        __syncthreads();
    }

    // ---- epilogue: demod scale + bias -> fp16 g_yh ----
#pragma unroll
    for (int mt = 0; mt < 2; mt++) {
        int oA = o0 + wm * 32 + mt * 16 + grp;
        int oB = oA + 8;
        float scA = g_scale[b * COUT + oA], bbA = conv_b[oA];
        float scB = g_scale[b * COUT + oB], bbB = conv_b[oB];
#pragma unroll
        for (int nt = 0; nt < 8; nt++) {
            int l = l0 + wn * 64 + nt * 8 + 2 * tig;
            __half2 vA = __floats2half2_rn(fmaf(acc[mt][nt][0], scA, bbA),
                                           fmaf(acc[mt][nt][1], scA, bbA));
            __half2 vB = __floats2half2_rn(fmaf(acc[mt][nt][2], scB, bbB),
                                           fmaf(acc[mt][nt][3], scB, bbB));
            *(__half2*)&g_yh[((size_t)(b * COUT + oA)) * LEN + l] = vA;
            *(__half2*)&g_yh[((size_t)(b * COUT + oB)) * LEN + l] = vB;
        }
    }
}

// ---------------- K7: resample, register-blocked ---------------------------
__global__ void __launch_bounds__(256)
resample_kernel(float* __restrict__ out, Filt F) {
    __shared__ float ysm[2064];            // [8 pad | 2048 | 8 pad]
    __shared__ float ue[2064], uo[2064];
    int bc = blockIdx.x;
    int t  = threadIdx.x;
    const __half* yrow = g_yh + (size_t)bc * LEN;

    if (t < 8) {
        ysm[t] = 0.f; ysm[2056 + t] = 0.f;
        ue[t]  = 0.f; ue[2056 + t]  = 0.f;
        uo[t]  = 0.f; uo[2056 + t]  = 0.f;
    }
    {
        uint4 v = ((const uint4*)yrow)[t];
        __half2* hp = (__half2*)&v;
        float2 p0 = __half22float2(hp[0]);
        float2 p1 = __half22float2(hp[1]);
        float2 p2 = __half22float2(hp[2]);
        float2 p3 = __half22float2(hp[3]);
        *(float4*)&ysm[8 + 8 * t]     = make_float4(p0.x, p0.y, p1.x, p1.y);
        *(float4*)&ysm[8 + 8 * t + 4] = make_float4(p2.x, p2.y, p3.x, p3.y);
    }
    __syncthreads();

    const float s2 = 1.41421356237f;
    {
        float w[16];
        *(float4*)&w[0]  = *(const float4*)&ysm[8 * t + 4];
        *(float4*)&w[4]  = *(const float4*)&ysm[8 * t + 8];
        *(float4*)&w[8]  = *(const float4*)&ysm[8 * t + 12];
        *(float4*)&w[12] = *(const float4*)&ysm[8 * t + 16];
        float e[8], o8[8];
#pragma unroll
        for (int p = 0; p < 8; p++) {
            float ev = 0.f, ov = 0.f;
#pragma unroll
            for (int j = 0; j < 9; j++) ev = fmaf(F.up[2 * j], w[p + j], ev);
#pragma unroll
            for (int j = 0; j < 8; j++) ov = fmaf(F.up[2 * j + 1], w[p + 1 + j], ov);
            e[p]  = (ev > 0.f ? ev : 0.1f * ev) * s2;
            o8[p] = (ov > 0.f ? ov : 0.1f * ov) * s2;
        }
        *(float4*)&ue[8 + 8 * t]     = make_float4(e[0], e[1], e[2], e[3]);
        *(float4*)&ue[8 + 8 * t + 4] = make_float4(e[4], e[5], e[6], e[7]);
        *(float4*)&uo[8 + 8 * t]     = make_float4(o8[0], o8[1], o8[2], o8[3]);
        *(float4*)&uo[8 + 8 * t + 4] = make_float4(o8[4], o8[5], o8[6], o8[7]);
    }
    __syncthreads();

    {
        float we[16], wo[16];
        *(float4*)&we[0]  = *(const float4*)&ue[8 * t + 4];
        *(float4*)&we[4]  = *(const float4*)&ue[8 * t + 8];
        *(float4*)&we[8]  = *(const float4*)&ue[8 * t + 12];
        *(float4*)&we[12] = *(const float4*)&ue[8 * t + 16];
        *(float4*)&wo[0]  = *(const float4*)&uo[8 * t + 4];
        *(float4*)&wo[4]  = *(const float4*)&uo[8 * t + 8];
        *(float4*)&wo[8]  = *(const float4*)&uo[8 * t + 12];
        *(float4*)&wo[12] = *(const float4*)&uo[8 * t + 16];
        float z[8];
#pragma unroll
        for (int p = 0; p < 8; p++) {
            float zv = 0.f;
#pragma unroll
            for (int j = 0; j < 9; j++) zv = fmaf(F.dn[2 * j], we[p + j], zv);
#pragma unroll
            for (int j = 0; j < 8; j++) zv = fmaf(F.dn[2 * j + 1], wo[p + j], zv);
            z[p] = zv;
        }
        float* orow = out + (size_t)bc * LEN + 8 * t;
        *(float4*)&orow[0] = make_float4(z[0], z[1], z[2], z[3]);
        *(float4*)&orow[4] = make_float4(z[4], z[5], z[6], z[7]);
    }
}

// ---------------- host: Kaiser-sinc filter ---------------------------------
static double bessel_i0(double x) {
    double s = 1.0, term = 1.0;
    for (int k = 1; k < 64; k++) {
        double h = x / (2.0 * k);
        term *= h * h;
        s += term;
        if (term < 1e-18 * s) break;
    }
    return s;
}
static void make_filter(float* f) {
    const double PI = 3.14159265358979323846;
    double i0b = bessel_i0(2.5);
    for (int i = 0; i < 17; i++) {
        int n = i - 8;
        float fv;
        if (n == 0) fv = 0.5f;
        else fv = (float)sin(0.5 * PI * (double)n) / ((float)(PI * (double)n) + 1e-8f);
        double r = (double)n / 8.0;
        double win = bessel_i0(2.5 * sqrt(1.0 - r * r)) / i0b;
        f[i] = (float)win * fv;
    }
}

// ---------------- launcher -------------------------------------------------
extern "C" void kernel_launch(void* const* d_in, const int* in_sizes, int n_in,
                              void* d_out, int out_size) {
    const float* x        = (const float*)d_in[0];
    const float* w        = (const float*)d_in[1];
    const float* affine_w = (const float*)d_in[2];
    const float* affine_b = (const float*)d_in[3];
    const float* conv_w   = (const float*)d_in[4];
    const float* conv_b   = (const float*)d_in[5];
    const float* norm_ema = (const float*)d_in[6];
    float* out = (float*)d_out;

    Filt F;
    make_filter(F.up);
    make_filter(F.dn);

    cudaFuncSetAttribute(conv_mma_kernel,
                         cudaFuncAttributeMaxDynamicSharedMemorySize, CONV_SMEM);

    cond_kernel<<<1024, 256>>>(w, affine_w, affine_b);
    reduce_cond_kernel<<<1, 256>>>();
    scale_s_kernel<<<32, 256>>>(norm_ema);
    wdemod_kernel<<<COUT, 128>>>(conv_w);
    split_w_kernel<<<(3 * COUT * CIN + 255) / 256, 256>>>(conv_w);
    dim3 tgrid(LEN / 32, CIN / 32, BS);
    transpose_x_kernel<<<tgrid, 256>>>(x);

    dim3 cgrid(LEN / BLT, COUT / BO, BS);
    conv_mma_kernel<<<cgrid, 512, CONV_SMEM>>>(conv_b);

    resample_kernel<<<BS * COUT, 256>>>(out, F);
}